// round 17
// baseline (speedup 1.0000x reference)
#include <cuda_runtime.h>
#include <cuda_bf16.h>
#include <cstdint>

// Problem constants (shape-fixed problem)
#define BB 2
#define LL 1024
#define D_SEQ 21
#define D_EMB 64
#define D_MODEL 128
#define ROWS (BB * LL)           // 2048

#define NWARP 8
#define NCHUNK 16
#define JPB (LL / NCHUNK)       // 64 j's per block
#define JPW (JPB / NWARP)       // 8 j's per warp
#define GRID (ROWS * NCHUNK)    // 32768 blocks

// Per-symbol separable tables (seq values are in [0, 21)).
// g_TQ is only 10.75 KB -> L1-resident per SM via __ldg.
__device__ float4 g_TP[D_SEQ * (D_MODEL / 4)];   // T_P[s,d] = bias[d] + sum_c emb[s,c]*W[d,c]
__device__ float4 g_TQ[D_SEQ * (D_MODEL / 4)];   // T_Q[s,d] = sum_c emb[s,c]*W[d,64+c]
__device__ float4 g_W128[D_MODEL / 4];           // packed W[:,128] column

// Producer/consumer flag + replay-reset counter. Zero-initialized at module
// load; the LAST finishing block restores both to 0, so every graph replay
// observes identical initial state (same work every call).
__device__ unsigned int g_flag = 0;   // counts table-producer arrivals (0..21)
__device__ unsigned int g_done = 0;   // counts finished blocks (0..GRID)

// ---------------------------------------------------------------------------
// Fused kernel.
//   Blocks 0..20: produce table row for symbol s = blockIdx.x, then arrive.
//   ALL blocks: spin until 21 arrivals, then do the R15 pair hot loop
//   (unchanged: zero-prologue, L1-resident table, __stcs streaming stores).
// out[b,i,j,d] = T_P[seq_i,d] + T_Q[seq_j,d] + log(|idx_i-idx_j|+1)*W128[d]
// ---------------------------------------------------------------------------
__global__ __launch_bounds__(256) void pair_fused_kernel(
    const int* __restrict__ seq,
    const int* __restrict__ idx,
    const float* __restrict__ emb,     // [21, 64]
    const float* __restrict__ W,       // [128, 129] row-major
    const float* __restrict__ bias,    // [128]
    float4* __restrict__ out)
{
    const int blk = blockIdx.x;

    // ---- Producer phase: first 21 blocks build the per-symbol tables ----
    if (blk < D_SEQ) {
        const int s = blk;
        const int d = threadIdx.x;
        __shared__ float e[D_EMB];
        if (d < D_EMB) e[d] = __ldg(emb + s * D_EMB + d);
        __syncthreads();
        if (d < D_MODEL) {
            const float* wrow = W + d * 129;
            float accP = __ldg(bias + d);
            float accQ = 0.0f;
#pragma unroll
            for (int c = 0; c < D_EMB; c++) {
                accP = fmaf(e[c], __ldg(wrow + c), accP);
                accQ = fmaf(e[c], __ldg(wrow + D_EMB + c), accQ);
            }
            ((float*)g_TP)[s * D_MODEL + d] = accP;
            ((float*)g_TQ)[s * D_MODEL + d] = accQ;
            if (s == 0) ((float*)g_W128)[d] = __ldg(wrow + 2 * D_EMB);
        }
        __threadfence();                 // each thread: make table stores GPU-visible
        __syncthreads();
        if (threadIdx.x == 0) {
            asm volatile("red.release.gpu.global.add.u32 [%0], 1;"
                         :: "l"(&g_flag) : "memory");
        }
    }

    // ---- Pair setup (input reads only; independent of tables) ----
    const int rowi = blk >> 4;              // b*L + i
    const int chunk = blk & (NCHUNK - 1);
    const int b = rowi >> 10;
    const int w = threadIdx.x >> 5;
    const int t = threadIdx.x & 31;

    const int idx_i = __ldg(idx + rowi);
    const int si = __ldg(seq + rowi);
    const int* __restrict__ idxb = idx + b * LL;
    const int* __restrict__ seqb = seq + b * LL;
    float4* __restrict__ outb = out + (size_t)rowi * LL * 32;

    // ---- Spin until all 21 producer blocks have arrived ----
    if (threadIdx.x == 0) {
        unsigned int v;
        do {
            asm volatile("ld.acquire.gpu.global.u32 %0, [%1];"
                         : "=r"(v) : "l"(&g_flag) : "memory");
            if (v >= D_SEQ) break;
            __nanosleep(64);
        } while (true);
    }
    __syncthreads();                        // broadcast release to whole block

    // ---- Pair hot loop (identical to R15 best: 140.5us, DRAM 91%) ----
    const float4 p4 = __ldg(&g_TP[si * 32 + t]);
    const float4 w4 = __ldg(&g_W128[t]);

    const int j0 = chunk * JPB + w * JPW;
#pragma unroll 4
    for (int k = 0; k < JPW; k++) {
        const int j = j0 + k;
        const int sj = __ldg(seqb + j);
        const int idx_j = __ldg(idxb + j);
        const float s = __logf(fabsf((float)(idx_i - idx_j)) + 1.0f);
        const float4 q = __ldg(&g_TQ[sj * 32 + t]);   // L1-resident table
        float4 o;
        o.x = fmaf(s, w4.x, p4.x + q.x);
        o.y = fmaf(s, w4.y, p4.y + q.y);
        o.z = fmaf(s, w4.z, p4.z + q.z);
        o.w = fmaf(s, w4.w, p4.w + q.w);
        __stcs(&outb[(size_t)j * 32 + t], o);
    }

    // ---- Replay reset: last block to finish restores flag state to 0 ----
    __syncthreads();
    if (threadIdx.x == 0) {
        unsigned int prev;
        asm volatile("atom.acq_rel.gpu.global.add.u32 %0, [%1], 1;"
                     : "=r"(prev) : "l"(&g_done) : "memory");
        if (prev == GRID - 1) {
            asm volatile("st.relaxed.gpu.global.u32 [%0], 0;" :: "l"(&g_done) : "memory");
            asm volatile("st.release.gpu.global.u32 [%0], 0;" :: "l"(&g_flag) : "memory");
        }
    }
}

// ---------------------------------------------------------------------------
// Launch: inputs per metadata order: seq(int32), idx(int32), emb_table(f32),
// W(f32 [128,129]), b(f32 [128]). Output: f32 [2,1024,1024,128].
// Single fused launch: saves the table kernel's launch latency + the
// inter-kernel drain (~5-7us measured gap in the two-kernel form).
// ---------------------------------------------------------------------------
extern "C" void kernel_launch(void* const* d_in, const int* in_sizes, int n_in,
                              void* d_out, int out_size)
{
    const int*   seq  = (const int*)d_in[0];
    const int*   idx  = (const int*)d_in[1];
    const float* emb  = (const float*)d_in[2];
    const float* W    = (const float*)d_in[3];
    const float* bias = (const float*)d_in[4];
    float4* out = (float4*)d_out;

    pair_fused_kernel<<<GRID, 256>>>(seq, idx, emb, W, bias, out);
}